// round 1
// baseline (speedup 1.0000x reference)
#include <cuda_runtime.h>
#include <cstdint>

// CRF forward log-partition.
// B=512, T=1024, L=64. One warp per batch, probability-domain recurrence:
//   p_{t+1} = (E @ p_t) * exp2(logit*log2e - k),  E = exp(trans) in registers,
//   C += k*ln2 (k = exponent of max p, applied next step -> exact rescale).
// Final: logZ = C + log( sum_j p[j] * exp(trans[63,j]) ).

#define CRF_B 512
#define CRF_T 1024
#define CRF_L 64
#define C_LOG2E 1.4426950408889634f
#define C_LN2   0.6931471805599453f

__device__ __forceinline__ float ex2f(float x) {
    float r; asm("ex2.approx.f32 %0, %1;" : "=f"(r) : "f"(x)); return r;
}
__device__ __forceinline__ unsigned long long packf2(float lo, float hi) {
    unsigned long long r;
    asm("mov.b64 %0, {%1, %2};" : "=l"(r) : "f"(lo), "f"(hi));
    return r;
}
__device__ __forceinline__ void unpackf2(unsigned long long v, float& lo, float& hi) {
    asm("mov.b64 {%0, %1}, %2;" : "=f"(lo), "=f"(hi) : "l"(v));
}
#define FMA2(acc, a, b) \
    asm("fma.rn.f32x2 %0, %1, %2, %0;" : "+l"(acc) : "l"(a), "l"(b))
#define ADD2(acc, a) \
    asm("add.rn.f32x2 %0, %0, %1;" : "+l"(acc) : "l"(a))

// One CRF step for one warp. Reads p from sp_r (all 64 values, broadcast LDS.64
// pairs), writes new p to sp_w. lg = (logit[t,2l], logit[t,2l+1]).
__device__ __forceinline__ void crf_step(
    float2 lg,
    const unsigned long long (&Ea)[32],
    const unsigned long long (&Eb)[32],
    const float2* __restrict__ sp_r,
    float2* __restrict__ sp_w,
    int lane, float& c, float& kf)
{
    unsigned long long a0 = 0ull, a1 = 0ull, b0 = 0ull, b1 = 0ull;
#pragma unroll
    for (int jj = 0; jj < 32; jj += 2) {
        unsigned long long p0 =
            *reinterpret_cast<const unsigned long long*>(sp_r + jj);
        unsigned long long p1 =
            *reinterpret_cast<const unsigned long long*>(sp_r + jj + 1);
        FMA2(a0, Ea[jj],     p0);
        FMA2(b0, Eb[jj],     p0);
        FMA2(a1, Ea[jj + 1], p1);
        FMA2(b1, Eb[jj + 1], p1);
    }
    ADD2(a0, a1);
    ADD2(b0, b1);
    float ax, ay, bx, by;
    unpackf2(a0, ax, ay);
    unpackf2(b0, bx, by);
    float sA = ax + ay;                 // s[2*lane]
    float sB = bx + by;                 // s[2*lane+1]

    // elogit with previous step's power-of-2 rescale folded in.
    float elA = ex2f(fmaf(lg.x, C_LOG2E, -kf));
    float elB = ex2f(fmaf(lg.y, C_LOG2E, -kf));
    float pA = sA * elA;
    float pB = sB * elB;

    sp_w[lane] = make_float2(pA, pB);

    // Account for the scale we just APPLIED, then compute next step's k.
    c = fmaf(kf, C_LN2, c);
    float m = fmaxf(pA, pB);            // all p > 0 -> uint compare == float compare
    unsigned mu = __reduce_max_sync(0xffffffffu, __float_as_uint(m));
    kf = (float)((int)(mu >> 23) - 127);

    __syncwarp();
}

__global__ void __launch_bounds__(128)
crf_fwd_kernel(const float* __restrict__ logits,
               const int*   __restrict__ lens,
               const float* __restrict__ trans,
               float*       __restrict__ out)
{
    __shared__ float2 sp[4][2][32];     // [warp][double-buffer][j-pair]

    const int w    = threadIdx.x >> 5;
    const int lane = threadIdx.x & 31;
    const int b    = blockIdx.x * 4 + w;           // grid=128 -> b < 512 always

    // ---- Load E = exp(trans) into registers (rows 2*lane and 2*lane+1) ----
    unsigned long long Ea[32], Eb[32];
    const float* ra = trans + (2 * lane)     * CRF_L;
    const float* rb = trans + (2 * lane + 1) * CRF_L;
#pragma unroll
    for (int jj = 0; jj < 32; jj++) {
        Ea[jj] = packf2(expf(ra[2 * jj]), expf(ra[2 * jj + 1]));
        Eb[jj] = packf2(expf(rb[2 * jj]), expf(rb[2 * jj + 1]));
    }
    // stop-row (63) entries matching this lane's owned p pair (2l, 2l+1)
    const float2 e63 = make_float2(expf(trans[63 * CRF_L + 2 * lane]),
                                   expf(trans[63 * CRF_L + 2 * lane + 1]));

    // ---- init p: delta at start label 62 ----
    sp[w][0][lane] = make_float2((2 * lane == 62) ? 1.0f : 0.0f,
                                 (2 * lane + 1 == 62) ? 1.0f : 0.0f);
    __syncwarp();

    float c  = 0.0f;
    float kf = 0.0f;
    const int len = lens[b];

    const float2* lgp =
        reinterpret_cast<const float2*>(logits + (size_t)b * CRF_T * CRF_L) + lane;
    // lgp + t*32 -> (logit[b,t,2l], logit[b,t,2l+1])

    // 4-deep prefetch of logit pairs (covers ~600cyc DRAM latency)
    float2 q0, q1, q2, q3;
    if (len > 0) q0 = __ldg(lgp);
    if (len > 1) q1 = __ldg(lgp + 32);
    if (len > 2) q2 = __ldg(lgp + 64);
    if (len > 3) q3 = __ldg(lgp + 96);

    int t = 0;
    for (; t + 4 <= len; t += 4) {
        float2 g;
        g = q0; if (t + 4 < len) q0 = __ldg(lgp + (size_t)(t + 4) * 32);
        crf_step(g, Ea, Eb, sp[w][0], sp[w][1], lane, c, kf);
        g = q1; if (t + 5 < len) q1 = __ldg(lgp + (size_t)(t + 5) * 32);
        crf_step(g, Ea, Eb, sp[w][1], sp[w][0], lane, c, kf);
        g = q2; if (t + 6 < len) q2 = __ldg(lgp + (size_t)(t + 6) * 32);
        crf_step(g, Ea, Eb, sp[w][0], sp[w][1], lane, c, kf);
        g = q3; if (t + 7 < len) q3 = __ldg(lgp + (size_t)(t + 7) * 32);
        crf_step(g, Ea, Eb, sp[w][1], sp[w][0], lane, c, kf);
    }
    for (; t < len; ++t) {              // <=3 remainder steps (direct loads)
        float2 g = __ldg(lgp + (size_t)t * 32);
        if (t & 1) crf_step(g, Ea, Eb, sp[w][1], sp[w][0], lane, c, kf);
        else       crf_step(g, Ea, Eb, sp[w][0], sp[w][1], lane, c, kf);
    }

    // ---- finalize: logZ = c + log( sum_j p[j] * E[63,j] ) ----
    __syncwarp();
    float2 pw = sp[w][len & 1][lane];
    float part = e63.x * pw.x + e63.y * pw.y;
#pragma unroll
    for (int o = 16; o > 0; o >>= 1)
        part += __shfl_xor_sync(0xffffffffu, part, o);
    if (lane == 0)
        out[b] = c + __logf(part);
}

extern "C" void kernel_launch(void* const* d_in, const int* in_sizes, int n_in,
                              void* d_out, int out_size)
{
    const float* logits = (const float*)d_in[0];   // [512,1024,64] f32
    const int*   lens   = (const int*)  d_in[1];   // [512] i32
    const float* trans  = (const float*)d_in[2];   // [64,64] f32
    float* out = (float*)d_out;                    // [512] f32

    crf_fwd_kernel<<<CRF_B / 4, 128>>>(logits, lens, trans, out);
}